// round 1
// baseline (speedup 1.0000x reference)
#include <cuda_runtime.h>
#include <math.h>

#define NUM_HEADS  8
#define NUM_LEVELS 4
#define NUM_POINTS 4
#define HEAD_DIM   32
#define EMBED      256
#define BS_        8
#define LQ_        900
#define LEN_V_     21760
#define NQ   (BS_*LQ_)        // 7200
#define MV   (BS_*LEN_V_)     // 174080

// -------- scratch (device globals; no allocations allowed) --------
__device__ float  g_v  [(size_t)MV*EMBED];          // projected value, 178 MB
__device__ float  g_off[(size_t)NQ*256];
__device__ float  g_aw [(size_t)NQ*128];
__device__ float4 g_samp[(size_t)NQ*NUM_HEADS*16];  // (locx, locy, weight, _)
__device__ float  g_mid[(size_t)NQ*EMBED];

// =================== fp32 SGEMM: C = A(MxK) * B(KxN) + bias ===================
#define BM 128
#define BN 128
#define BKT 16

__global__ __launch_bounds__(256) void sgemm_bias(
    const float* __restrict__ A, const float* __restrict__ B,
    const float* __restrict__ bias, float* __restrict__ C,
    int M, int N, int K)
{
    __shared__ float As[BKT][BM];
    __shared__ float Bs[BKT][BN];
    const int tid  = threadIdx.x;
    const int brow = blockIdx.y * BM;
    const int bcol = blockIdx.x * BN;
    const int tr   = (tid >> 4) * 8;   // row offset in tile
    const int tc   = (tid & 15) * 8;   // col offset in tile

    float acc[8][8] = {};
    float afr[8], bfr[8];

    for (int kt = 0; kt < K; kt += BKT) {
        // A tile: BM x BKT, stored transposed As[k][m]
        #pragma unroll
        for (int i = 0; i < 2; i++) {
            int idx  = tid + i * 256;            // float4 index [0,512)
            int arow = idx >> 2;
            int ac4  = idx & 3;
            int grow = brow + arow;
            float4 v = make_float4(0.f, 0.f, 0.f, 0.f);
            if (grow < M)
                v = *reinterpret_cast<const float4*>(&A[(long)grow * K + kt + ac4 * 4]);
            As[ac4*4+0][arow] = v.x;
            As[ac4*4+1][arow] = v.y;
            As[ac4*4+2][arow] = v.z;
            As[ac4*4+3][arow] = v.w;
        }
        // B tile: BKT x BN (row-major, direct)
        #pragma unroll
        for (int i = 0; i < 2; i++) {
            int idx  = tid + i * 256;
            int krow = idx >> 5;
            int bc4  = idx & 31;
            float4 v = *reinterpret_cast<const float4*>(&B[(long)(kt + krow) * N + bcol + bc4 * 4]);
            *reinterpret_cast<float4*>(&Bs[krow][bc4 * 4]) = v;
        }
        __syncthreads();
        #pragma unroll
        for (int k = 0; k < BKT; k++) {
            *reinterpret_cast<float4*>(&afr[0]) = *reinterpret_cast<const float4*>(&As[k][tr]);
            *reinterpret_cast<float4*>(&afr[4]) = *reinterpret_cast<const float4*>(&As[k][tr + 4]);
            *reinterpret_cast<float4*>(&bfr[0]) = *reinterpret_cast<const float4*>(&Bs[k][tc]);
            *reinterpret_cast<float4*>(&bfr[4]) = *reinterpret_cast<const float4*>(&Bs[k][tc + 4]);
            #pragma unroll
            for (int i = 0; i < 8; i++)
                #pragma unroll
                for (int j = 0; j < 8; j++)
                    acc[i][j] += afr[i] * bfr[j];
        }
        __syncthreads();
    }

    float bv[8];
    *reinterpret_cast<float4*>(&bv[0]) = *reinterpret_cast<const float4*>(&bias[bcol + tc]);
    *reinterpret_cast<float4*>(&bv[4]) = *reinterpret_cast<const float4*>(&bias[bcol + tc + 4]);
    #pragma unroll
    for (int i = 0; i < 8; i++) {
        int grow = brow + tr + i;
        if (grow < M) {
            float4 o0 = make_float4(acc[i][0]+bv[0], acc[i][1]+bv[1], acc[i][2]+bv[2], acc[i][3]+bv[3]);
            float4 o1 = make_float4(acc[i][4]+bv[4], acc[i][5]+bv[5], acc[i][6]+bv[6], acc[i][7]+bv[7]);
            *reinterpret_cast<float4*>(&C[(long)grow * N + bcol + tc])     = o0;
            *reinterpret_cast<float4*>(&C[(long)grow * N + bcol + tc + 4]) = o1;
        }
    }
}

// =================== softmax over 16 pts + sampling-loc precompute ===================
__global__ void softmax_loc(const float* __restrict__ refp)
{
    int t = blockIdx.x * blockDim.x + threadIdx.x;
    if (t >= NQ * NUM_HEADS) return;
    int bq = t >> 3;
    int h  = t & 7;

    const float* aw = &g_aw[(long)bq * 128 + h * 16];
    float m = -1e30f;
    float e[16];
    #pragma unroll
    for (int i = 0; i < 16; i++) m = fmaxf(m, aw[i]);
    float s = 0.f;
    #pragma unroll
    for (int i = 0; i < 16; i++) { e[i] = expf(aw[i] - m); s += e[i]; }
    float inv = 1.f / s;

    const float invWH[4] = {1.f/128.f, 1.f/64.f, 1.f/32.f, 1.f/16.f};
    const float* offp = &g_off[(long)bq * 256 + h * 32];
    float4* out = &g_samp[(long)t * 16];

    #pragma unroll
    for (int l = 0; l < 4; l++) {
        float rx = refp[((long)bq * 4 + l) * 2 + 0];
        float ry = refp[((long)bq * 4 + l) * 2 + 1];
        #pragma unroll
        for (int p = 0; p < 4; p++) {
            float ox = offp[(l * 4 + p) * 2 + 0];
            float oy = offp[(l * 4 + p) * 2 + 1];
            out[l * 4 + p] = make_float4(rx + ox * invWH[l],
                                         ry + oy * invWH[l],
                                         e[l * 4 + p] * inv, 0.f);
        }
    }
}

// =================== bilinear gather + weighted accumulate ===================
// one warp per (b, q, h); lane = head_dim element -> each corner read = 128B coalesced line
__global__ __launch_bounds__(256) void msda_sample()
{
    int warp = (blockIdx.x * blockDim.x + threadIdx.x) >> 5;
    int lane = threadIdx.x & 31;
    if (warp >= NQ * NUM_HEADS) return;
    int h  = warp & 7;
    int bq = warp >> 3;
    int b  = bq / LQ_;

    const float4* samp = &g_samp[(long)warp * 16];
    const float* vb = g_v + (long)b * LEN_V_ * EMBED + h * HEAD_DIM + lane;

    const int   Wl[4]     = {128, 64, 32, 16};
    const int   starts[4] = {0, 16384, 20480, 21504};

    float acc = 0.f;
    #pragma unroll
    for (int l = 0; l < 4; l++) {
        const int W = Wl[l];
        const int H = W;
        const float* vl = vb + (long)starts[l] * EMBED;
        #pragma unroll
        for (int p = 0; p < 4; p++) {
            float4 sp = samp[l * 4 + p];     // uniform across warp
            float px = sp.x * (float)W - 0.5f;
            float py = sp.y * (float)H - 0.5f;
            float x0f = floorf(px), y0f = floorf(py);
            float dx = px - x0f, dy = py - y0f;
            int x0 = (int)x0f, y0 = (int)y0f;
            float w00 = (1.f - dx) * (1.f - dy) * sp.z;
            float w10 = dx * (1.f - dy) * sp.z;
            float w01 = (1.f - dx) * dy * sp.z;
            float w11 = dx * dy * sp.z;
            bool xv0 = (x0 >= 0) && (x0 < W);
            bool xv1 = (x0 >= -1) && (x0 + 1 < W);
            bool yv0 = (y0 >= 0) && (y0 < H);
            bool yv1 = (y0 >= -1) && (y0 + 1 < H);
            if (xv0 && yv0) acc += w00 * vl[((long)y0 * W + x0) * EMBED];
            if (xv1 && yv0) acc += w10 * vl[((long)y0 * W + x0 + 1) * EMBED];
            if (xv0 && yv1) acc += w01 * vl[((long)(y0 + 1) * W + x0) * EMBED];
            if (xv1 && yv1) acc += w11 * vl[((long)(y0 + 1) * W + x0 + 1) * EMBED];
        }
    }
    g_mid[(long)bq * EMBED + h * HEAD_DIM + lane] = acc;
}

// =================== launch ===================
extern "C" void kernel_launch(void* const* d_in, const int* in_sizes, int n_in,
                              void* d_out, int out_size)
{
    const float* query   = (const float*)d_in[0];
    const float* refp    = (const float*)d_in[1];
    const float* value   = (const float*)d_in[2];
    const float* w_value = (const float*)d_in[3];
    const float* b_value = (const float*)d_in[4];
    const float* w_off   = (const float*)d_in[5];
    const float* b_off   = (const float*)d_in[6];
    const float* w_attn  = (const float*)d_in[7];
    const float* b_attn  = (const float*)d_in[8];
    const float* w_out   = (const float*)d_in[9];
    const float* b_out   = (const float*)d_in[10];
    float* out = (float*)d_out;

    float *pv, *poff, *paw, *pmid;
    cudaGetSymbolAddress((void**)&pv,   g_v);
    cudaGetSymbolAddress((void**)&poff, g_off);
    cudaGetSymbolAddress((void**)&paw,  g_aw);
    cudaGetSymbolAddress((void**)&pmid, g_mid);

    // 1) v = value @ w_value + b_value   (174080 x 256 x 256)
    {
        dim3 grid(EMBED / BN, (MV + BM - 1) / BM);
        sgemm_bias<<<grid, 256>>>(value, w_value, b_value, pv, MV, EMBED, EMBED);
    }
    // 2) off = query @ w_off + b_off     (7200 x 256 x 256)
    {
        dim3 grid(256 / BN, (NQ + BM - 1) / BM);
        sgemm_bias<<<grid, 256>>>(query, w_off, b_off, poff, NQ, 256, EMBED);
    }
    // 3) aw = query @ w_attn + b_attn    (7200 x 128 x 256)
    {
        dim3 grid(128 / BN, (NQ + BM - 1) / BM);
        sgemm_bias<<<grid, 256>>>(query, w_attn, b_attn, paw, NQ, 128, EMBED);
    }
    // 4) softmax + sampling locations
    {
        int total = NQ * NUM_HEADS;
        softmax_loc<<<(total + 255) / 256, 256>>>(refp);
    }
    // 5) bilinear sample + weighted sum  (one warp per (b,q,h))
    {
        int warps = NQ * NUM_HEADS;                 // 57600
        msda_sample<<<(warps * 32 + 255) / 256, 256>>>();
    }
    // 6) out = mid @ w_out + b_out -> d_out
    {
        dim3 grid(EMBED / BN, (NQ + BM - 1) / BM);
        sgemm_bias<<<grid, 256>>>(pmid, w_out, b_out, out, NQ, EMBED, EMBED);
    }
}

// round 2
// speedup vs baseline: 1.5698x; 1.5698x over previous
#include <cuda_runtime.h>
#include <math.h>
#include <stdint.h>

#define NUM_HEADS  8
#define NUM_LEVELS 4
#define NUM_POINTS 4
#define HEAD_DIM   32
#define EMBED      256
#define BS_        8
#define LQ_        900
#define LEN_V_     21760
#define NQ   (BS_*LQ_)        // 7200
#define MV   (BS_*LEN_V_)     // 174080

// -------- scratch (device globals; no allocations allowed) --------
__device__ float  g_v  [(size_t)MV*EMBED];          // projected value, 178 MB
__device__ float  g_off[(size_t)NQ*256];
__device__ float  g_aw [(size_t)NQ*128];
__device__ float4 g_samp[(size_t)NQ*NUM_HEADS*16];  // (locx, locy, weight, _)
__device__ float  g_mid[(size_t)NQ*EMBED];

// =================== TF32 tensor-core GEMM: C = A(MxK)*B(KxN) + bias ===================
// Block tile 128x128, K-tile 32, 8 warps (2M x 4N), warp tile 64x32,
// mma.sync.aligned.m16n8k8.row.col.f32.tf32.tf32.f32
#define BM 128
#define BN 128
#define BK 32

__device__ __forceinline__ uint32_t f2tf32(float f) {
    uint32_t u;
    asm("cvt.rna.tf32.f32 %0, %1;" : "=r"(u) : "f"(f));
    return u;
}

__device__ __forceinline__ void mma_tf32(float* c, const uint32_t* a, const uint32_t* b) {
    asm volatile(
        "mma.sync.aligned.m16n8k8.row.col.f32.tf32.tf32.f32 "
        "{%0,%1,%2,%3}, {%4,%5,%6,%7}, {%8,%9}, {%0,%1,%2,%3};\n"
        : "+f"(c[0]), "+f"(c[1]), "+f"(c[2]), "+f"(c[3])
        : "r"(a[0]), "r"(a[1]), "r"(a[2]), "r"(a[3]), "r"(b[0]), "r"(b[1]));
}

#define LDA (BK + 4)   // 36: bank = (4*row+col)%32 -> conflict-free fragment reads

__global__ __launch_bounds__(256) void tf32_gemm_bias(
    const float* __restrict__ A, const float* __restrict__ B,
    const float* __restrict__ bias, float* __restrict__ C,
    int M, int N, int K)
{
    __shared__ uint32_t As[BM][LDA];   // [m][k]  (tf32 bits)
    __shared__ uint32_t Bs[BN][LDA];   // [n][k]  (tf32 bits, B transposed)

    const int tid   = threadIdx.x;
    const int lane  = tid & 31;
    const int warp  = tid >> 5;
    const int warpM = warp >> 2;      // 0..1
    const int warpN = warp & 3;       // 0..3
    const int brow  = blockIdx.y * BM;
    const int bcol  = blockIdx.x * BN;
    const int g     = lane >> 2;      // group id 0..7
    const int tg    = lane & 3;       // thread-in-group 0..3

    float acc[4][4][4];
    #pragma unroll
    for (int i = 0; i < 4; i++)
        #pragma unroll
        for (int j = 0; j < 4; j++)
            #pragma unroll
            for (int r = 0; r < 4; r++) acc[i][j][r] = 0.f;

    for (int kt = 0; kt < K; kt += BK) {
        // ---- A tile: BM x BK (1024 float4, 4 per thread), cvt->tf32, [m][k]
        #pragma unroll
        for (int i = 0; i < 4; i++) {
            int idx  = tid + i * 256;
            int arow = idx >> 3;
            int ac4  = idx & 7;
            int grow = brow + arow;
            float4 v = make_float4(0.f, 0.f, 0.f, 0.f);
            if (grow < M)
                v = *reinterpret_cast<const float4*>(&A[(long)grow * K + kt + ac4 * 4]);
            As[arow][ac4*4+0] = f2tf32(v.x);
            As[arow][ac4*4+1] = f2tf32(v.y);
            As[arow][ac4*4+2] = f2tf32(v.z);
            As[arow][ac4*4+3] = f2tf32(v.w);
        }
        // ---- B tile: BK x BN (row-major global) -> Bs[n][k]
        #pragma unroll
        for (int i = 0; i < 4; i++) {
            int idx  = tid + i * 256;
            int krow = idx >> 5;           // 0..31
            int nc4  = idx & 31;           // 0..31 -> n = nc4*4..+3
            float4 v = *reinterpret_cast<const float4*>(&B[(long)(kt + krow) * N + bcol + nc4 * 4]);
            Bs[nc4*4+0][krow] = f2tf32(v.x);
            Bs[nc4*4+1][krow] = f2tf32(v.y);
            Bs[nc4*4+2][krow] = f2tf32(v.z);
            Bs[nc4*4+3][krow] = f2tf32(v.w);
        }
        __syncthreads();

        #pragma unroll
        for (int ks = 0; ks < BK / 8; ks++) {
            const int kb = ks * 8;
            uint32_t af[4][4], bf[4][2];
            #pragma unroll
            for (int mt = 0; mt < 4; mt++) {
                int rb = warpM * 64 + mt * 16;
                af[mt][0] = As[rb + g    ][kb + tg    ];
                af[mt][1] = As[rb + g + 8][kb + tg    ];
                af[mt][2] = As[rb + g    ][kb + tg + 4];
                af[mt][3] = As[rb + g + 8][kb + tg + 4];
            }
            #pragma unroll
            for (int nt = 0; nt < 4; nt++) {
                int nb = warpN * 32 + nt * 8;
                bf[nt][0] = Bs[nb + g][kb + tg    ];
                bf[nt][1] = Bs[nb + g][kb + tg + 4];
            }
            #pragma unroll
            for (int mt = 0; mt < 4; mt++)
                #pragma unroll
                for (int nt = 0; nt < 4; nt++)
                    mma_tf32(acc[mt][nt], af[mt], bf[nt]);
        }
        __syncthreads();
    }

    // ---- epilogue: + bias, guarded store
    #pragma unroll
    for (int mt = 0; mt < 4; mt++) {
        int row0 = brow + warpM * 64 + mt * 16 + g;
        #pragma unroll
        for (int nt = 0; nt < 4; nt++) {
            int col = bcol + warpN * 32 + nt * 8 + tg * 2;
            float b0 = bias[col], b1 = bias[col + 1];
            if (row0 < M) {
                float2 o = make_float2(acc[mt][nt][0] + b0, acc[mt][nt][1] + b1);
                *reinterpret_cast<float2*>(&C[(long)row0 * N + col]) = o;
            }
            if (row0 + 8 < M) {
                float2 o = make_float2(acc[mt][nt][2] + b0, acc[mt][nt][3] + b1);
                *reinterpret_cast<float2*>(&C[(long)(row0 + 8) * N + col]) = o;
            }
        }
    }
}

// =================== softmax over 16 pts + sampling-loc precompute ===================
__global__ void softmax_loc(const float* __restrict__ refp)
{
    int t = blockIdx.x * blockDim.x + threadIdx.x;
    if (t >= NQ * NUM_HEADS) return;
    int bq = t >> 3;
    int h  = t & 7;

    const float* aw = &g_aw[(long)bq * 128 + h * 16];
    float m = -1e30f;
    float e[16];
    #pragma unroll
    for (int i = 0; i < 16; i++) m = fmaxf(m, aw[i]);
    float s = 0.f;
    #pragma unroll
    for (int i = 0; i < 16; i++) { e[i] = expf(aw[i] - m); s += e[i]; }
    float inv = 1.f / s;

    const float invWH[4] = {1.f/128.f, 1.f/64.f, 1.f/32.f, 1.f/16.f};
    const float* offp = &g_off[(long)bq * 256 + h * 32];
    float4* out = &g_samp[(long)t * 16];

    #pragma unroll
    for (int l = 0; l < 4; l++) {
        float rx = refp[((long)bq * 4 + l) * 2 + 0];
        float ry = refp[((long)bq * 4 + l) * 2 + 1];
        #pragma unroll
        for (int p = 0; p < 4; p++) {
            float ox = offp[(l * 4 + p) * 2 + 0];
            float oy = offp[(l * 4 + p) * 2 + 1];
            out[l * 4 + p] = make_float4(rx + ox * invWH[l],
                                         ry + oy * invWH[l],
                                         e[l * 4 + p] * inv, 0.f);
        }
    }
}

// =================== bilinear gather + weighted accumulate ===================
// one warp per (b, q, h); lane = head_dim element -> each corner read = 128B coalesced line
__global__ __launch_bounds__(256) void msda_sample()
{
    int warp = (blockIdx.x * blockDim.x + threadIdx.x) >> 5;
    int lane = threadIdx.x & 31;
    if (warp >= NQ * NUM_HEADS) return;
    int h  = warp & 7;
    int bq = warp >> 3;
    int b  = bq / LQ_;

    const float4* samp = &g_samp[(long)warp * 16];
    const float* vb = g_v + (long)b * LEN_V_ * EMBED + h * HEAD_DIM + lane;

    const int   Wl[4]     = {128, 64, 32, 16};
    const int   starts[4] = {0, 16384, 20480, 21504};

    float acc = 0.f;
    #pragma unroll
    for (int l = 0; l < 4; l++) {
        const int W = Wl[l];
        const int H = W;
        const float* vl = vb + (long)starts[l] * EMBED;
        #pragma unroll
        for (int p = 0; p < 4; p++) {
            float4 sp = samp[l * 4 + p];     // uniform across warp
            float px = sp.x * (float)W - 0.5f;
            float py = sp.y * (float)H - 0.5f;
            float x0f = floorf(px), y0f = floorf(py);
            float dx = px - x0f, dy = py - y0f;
            int x0 = (int)x0f, y0 = (int)y0f;
            float w00 = (1.f - dx) * (1.f - dy) * sp.z;
            float w10 = dx * (1.f - dy) * sp.z;
            float w01 = (1.f - dx) * dy * sp.z;
            float w11 = dx * dy * sp.z;
            bool xv0 = (x0 >= 0) && (x0 < W);
            bool xv1 = (x0 >= -1) && (x0 + 1 < W);
            bool yv0 = (y0 >= 0) && (y0 < H);
            bool yv1 = (y0 >= -1) && (y0 + 1 < H);
            if (xv0 && yv0) acc += w00 * vl[((long)y0 * W + x0) * EMBED];
            if (xv1 && yv0) acc += w10 * vl[((long)y0 * W + x0 + 1) * EMBED];
            if (xv0 && yv1) acc += w01 * vl[((long)(y0 + 1) * W + x0) * EMBED];
            if (xv1 && yv1) acc += w11 * vl[((long)(y0 + 1) * W + x0 + 1) * EMBED];
        }
    }
    g_mid[(long)bq * EMBED + h * HEAD_DIM + lane] = acc;
}

// =================== launch ===================
extern "C" void kernel_launch(void* const* d_in, const int* in_sizes, int n_in,
                              void* d_out, int out_size)
{
    const float* query   = (const float*)d_in[0];
    const float* refp    = (const float*)d_in[1];
    const float* value   = (const float*)d_in[2];
    const float* w_value = (const float*)d_in[3];
    const float* b_value = (const float*)d_in[4];
    const float* w_off   = (const float*)d_in[5];
    const float* b_off   = (const float*)d_in[6];
    const float* w_attn  = (const float*)d_in[7];
    const float* b_attn  = (const float*)d_in[8];
    const float* w_out   = (const float*)d_in[9];
    const float* b_out   = (const float*)d_in[10];
    float* out = (float*)d_out;

    float *pv, *poff, *paw, *pmid;
    cudaGetSymbolAddress((void**)&pv,   g_v);
    cudaGetSymbolAddress((void**)&poff, g_off);
    cudaGetSymbolAddress((void**)&paw,  g_aw);
    cudaGetSymbolAddress((void**)&pmid, g_mid);

    // 1) v = value @ w_value + b_value   (174080 x 256 x 256)
    {
        dim3 grid(EMBED / BN, (MV + BM - 1) / BM);
        tf32_gemm_bias<<<grid, 256>>>(value, w_value, b_value, pv, MV, EMBED, EMBED);
    }
    // 2) off = query @ w_off + b_off     (7200 x 256 x 256)
    {
        dim3 grid(256 / BN, (NQ + BM - 1) / BM);
        tf32_gemm_bias<<<grid, 256>>>(query, w_off, b_off, poff, NQ, 256, EMBED);
    }
    // 3) aw = query @ w_attn + b_attn    (7200 x 128 x 256)
    {
        dim3 grid(128 / BN, (NQ + BM - 1) / BM);
        tf32_gemm_bias<<<grid, 256>>>(query, w_attn, b_attn, paw, NQ, 128, EMBED);
    }
    // 4) softmax + sampling locations
    {
        int total = NQ * NUM_HEADS;
        softmax_loc<<<(total + 255) / 256, 256>>>(refp);
    }
    // 5) bilinear sample + weighted sum  (one warp per (b,q,h))
    {
        int warps = NQ * NUM_HEADS;                 // 57600
        msda_sample<<<(warps * 32 + 255) / 256, 256>>>();
    }
    // 6) out = mid @ w_out + b_out -> d_out
    {
        dim3 grid(EMBED / BN, (NQ + BM - 1) / BM);
        tf32_gemm_bias<<<grid, 256>>>(pmid, w_out, b_out, out, NQ, EMBED, EMBED);
    }
}